// round 15
// baseline (speedup 1.0000x reference)
#include <cuda_runtime.h>
#include <cuda_fp16.h>
#include <cstdint>

// Problem constants
#define BB 64
#define TT 256
#define DD 512
#define HH 1024
#define N4H 4096   // 4*H
#define MM (BB*TT) // 16384
#define GRID 128   // persistent CTAs (co-resident)

// ---------------- device scratch ----------------
__device__ __half g_x16[(size_t)MM * DD];
__device__ __half g_WxT[(size_t)N4H * DD];
__device__ __half g_WhT[(size_t)N4H * HH];
__device__ float  g_XWb[(size_t)MM * N4H];   // layout [T][B][4H]
__device__ __half g_h16[2][BB * HH];
__device__ int    g_flags[GRID * 32];        // 128B-padded; 2 increments per step

// ---------------- helpers ----------------
__device__ __forceinline__ float sigm(float x) { return 1.f / (1.f + __expf(-x)); }

__device__ __forceinline__ void mma16816(float* c,
                                         uint32_t a0, uint32_t a1, uint32_t a2, uint32_t a3,
                                         uint32_t b0, uint32_t b1) {
    asm volatile(
        "mma.sync.aligned.m16n8k16.row.col.f32.f16.f16.f32 "
        "{%0,%1,%2,%3}, {%4,%5,%6,%7}, {%8,%9}, {%0,%1,%2,%3};\n"
        : "+f"(c[0]), "+f"(c[1]), "+f"(c[2]), "+f"(c[3])
        : "r"(a0), "r"(a1), "r"(a2), "r"(a3), "r"(b0), "r"(b1));
}

__device__ __forceinline__ void ldsm4(uint32_t& r0, uint32_t& r1, uint32_t& r2, uint32_t& r3,
                                      uint32_t addr) {
    asm volatile("ldmatrix.sync.aligned.m8n8.x4.shared.b16 {%0,%1,%2,%3}, [%4];"
                 : "=r"(r0), "=r"(r1), "=r"(r2), "=r"(r3) : "r"(addr));
}

// ---------------- dummy (ncu alignment: lstm = global launch #6) -------------
__global__ void noop_kernel() {}

// ---------------- prep ----------------
__global__ void prep_kernel(const float* __restrict__ x,
                            const float* __restrict__ W,
                            float* __restrict__ out) {
    size_t i0 = (size_t)blockIdx.x * blockDim.x + threadIdx.x;
    size_t stride = (size_t)gridDim.x * blockDim.x;
    for (size_t i = i0; i < GRID * 32; i += stride)
        g_flags[i] = 0;
    for (size_t i = i0; i < (size_t)MM * DD; i += stride)
        g_x16[i] = __float2half(x[i]);
    for (size_t i = i0; i < (size_t)N4H * DD; i += stride) {
        size_t n = i >> 9, k = i & 511;
        g_WxT[i] = __float2half(W[k * N4H + n]);
    }
    for (size_t i = i0; i < (size_t)N4H * HH; i += stride) {
        size_t n = i >> 10, k = i & 1023;
        g_WhT[i] = __float2half(W[(DD + k) * N4H + n]);
    }
    for (size_t i = i0; i < (size_t)BB * HH; i += stride) {
        out[i] = 0.f;
        g_h16[0][i] = __float2half(0.f);
        g_h16[1][i] = __float2half(0.f);
    }
}

// ---------------- precompute XWb = x @ Wx + b, output [T][B][4H] --------------
__global__ __launch_bounds__(128) void gemm_x_kernel(const float* __restrict__ bias) {
    __shared__ __half As[2][64 * 72];
    __shared__ __half Bs[2][64 * 72];
    const int tid = threadIdx.x;
    const int w = tid >> 5, lane = tid & 31;
    const int g = lane >> 2, tig = lane & 3;
    const int mt = blockIdx.y, nt = blockIdx.x;
    const int mbase = mt * 64;
    const int cw = nt * 64 + w * 16;

    const uint32_t AsS = (uint32_t)__cvta_generic_to_shared(&As[0][0]);
    const uint32_t BsS = (uint32_t)__cvta_generic_to_shared(&Bs[0][0]);
    const int aoff = (lane & 15) * 144 + ((lane >> 4) << 4);
    const int boff = ((lane & 7) + ((lane >> 4) & 1) * 8) * 144 + ((lane >> 3) & 1) * 16;

    float acc[4][2][4];
#pragma unroll
    for (int a = 0; a < 4; a++)
#pragma unroll
        for (int bq = 0; bq < 2; bq++)
#pragma unroll
            for (int e = 0; e < 4; e++) acc[a][bq][e] = 0.f;

    auto stage = [&](int c, int buf) {
        int kc = c * 64;
#pragma unroll
        for (int i = 0; i < 4; i++) {
            int idx = tid + i * 128;
            int r = idx >> 3, c8 = idx & 7;
            uint32_t da = (uint32_t)__cvta_generic_to_shared(&As[buf][r * 72 + c8 * 8]);
            const void* sa = &g_x16[(size_t)(mbase + r) * DD + kc + c8 * 8];
            asm volatile("cp.async.cg.shared.global [%0], [%1], 16;\n" :: "r"(da), "l"(sa));
            uint32_t db = (uint32_t)__cvta_generic_to_shared(&Bs[buf][r * 72 + c8 * 8]);
            const void* sb = &g_WxT[(size_t)(nt * 64 + r) * DD + kc + c8 * 8];
            asm volatile("cp.async.cg.shared.global [%0], [%1], 16;\n" :: "r"(db), "l"(sb));
        }
        asm volatile("cp.async.commit_group;\n" ::: "memory");
    };

    stage(0, 0);
    for (int c = 0; c < 8; c++) {
        __syncthreads();
        if (c < 7) {
            stage(c + 1, (c + 1) & 1);
            asm volatile("cp.async.wait_group 1;\n" ::: "memory");
        } else {
            asm volatile("cp.async.wait_group 0;\n" ::: "memory");
        }
        __syncthreads();
        const uint32_t Ab = AsS + (c & 1) * 9216;
        const uint32_t Bb = BsS + (c & 1) * 9216;
#pragma unroll
        for (int k0 = 0; k0 < 64; k0 += 16) {
            uint32_t b0, b1, b2, b3;
            ldsm4(b0, b1, b2, b3, Bb + w * 16 * 144 + k0 * 2 + boff);
#pragma unroll
            for (int mb = 0; mb < 4; mb++) {
                uint32_t a0, a1, a2, a3;
                ldsm4(a0, a1, a2, a3, Ab + mb * 2304 + k0 * 2 + aoff);
                mma16816(acc[mb][0], a0, a1, a2, a3, b0, b1);
                mma16816(acc[mb][1], a0, a1, a2, a3, b2, b3);
            }
        }
    }
#pragma unroll
    for (int mb = 0; mb < 4; mb++) {
#pragma unroll
        for (int nb = 0; nb < 2; nb++) {
            int col = cw + nb * 8 + 2 * tig;
            float2 bv = *(const float2*)&bias[col];
            int m0 = mbase + mb * 16 + g;
            int m1 = m0 + 8;
            size_t r0 = (size_t)((m0 & 255) * BB + (m0 >> 8));   // [t][b]
            size_t r1 = (size_t)((m1 & 255) * BB + (m1 >> 8));
            float2 v0 = {acc[mb][nb][0] + bv.x, acc[mb][nb][1] + bv.y};
            float2 v1 = {acc[mb][nb][2] + bv.x, acc[mb][nb][3] + bv.y};
            *(float2*)&g_XWb[r0 * N4H + col] = v0;
            *(float2*)&g_XWb[r1 * N4H + col] = v1;
        }
    }
}

// ---------------- persistent LSTM: k-partitioned warps, half-step waves -------
// Warp w owns k-eighth [128w,128w+128) (producers = CTAs [16w,16w+16)).
// Flags advance by 2 per step: 2t+1 after h(t+1) rows 0-31, 2t+2 after rows 32-63.
// Per step: pollA(>=2t-1) -> stage rows 0-31 -> MMA pass0 -> pollB(>=2t) ->
// stage rows 32-63 (flies during merge0/gates0) -> merge0 -> gates rows 0-31 ->
// release 2t+1 -> MMA pass1 -> merge1 -> gates rows 32-63 -> release 2t+2.
// SMEM: Wh_s 32 x 1032 halves (66048) | Hs 8 x 16384 (131072, XOR-swizzled)
//       zs 4 x 2048 f32 (32768)  -> total 229888 B
#define SM_WH   0
#define SM_HS   66048
#define SM_ZS   197120
#define SM_TOT  229888

__global__ __launch_bounds__(256, 1) void lstm_persistent_kernel(
        const int* __restrict__ seq_len, float* __restrict__ out) {
    extern __shared__ char smem_raw[];
    __half* Wh_s = (__half*)(smem_raw + SM_WH);
    float*  zs   = (float*)(smem_raw + SM_ZS);

    const int tid = threadIdx.x;
    const int w = tid >> 5, lane = tid & 31;
    const int g = lane >> 2, tig = lane & 3;
    const int j = blockIdx.x;                 // owns hidden units [8j, 8j+8)
    const int r15 = lane & 15;
    const int hi16 = (lane >> 4) << 4;        // 0 or 16 (k vs k+8 halves)
    const int copy = w & 3;                   // zs copy / pair id

    const uint32_t wbuf = (uint32_t)__cvta_generic_to_shared(smem_raw + SM_HS) + w * 16384;

    // Load Wh slice: 32 local cols (gate*8+unit), padded stride 1032 halves
    for (int idx = tid; idx < 4096; idx += 256) {
        int lc = idx >> 7;
        int kk = (idx & 127) * 8;
        int gg = lc >> 3, u = lc & 7;
        size_t gcol = (size_t)gg * HH + j * 8 + u;
        *(int4*)&Wh_s[lc * 1032 + kk] = *(const int4*)&g_WhT[gcol * HH + kk];
    }
    float cst[2] = {0.f, 0.f};
    int slr[2];
#pragma unroll
    for (int s = 0; s < 2; s++) slr[s] = seq_len[(tid + s * 256) >> 3];
    int* my_flag = &g_flags[j * 32];
    int* prod_flag = (lane < 16) ? &g_flags[(w * 16 + lane) * 32] : nullptr;
    __syncthreads();

    for (int t = 0; t < TT; t++) {
        const __half* __restrict__ h_read = g_h16[t & 1];
        __half* __restrict__ h_write = g_h16[(t + 1) & 1];
        const __half* __restrict__ hsrc = h_read + w * 128;  // this warp's k-eighth

        // ---- XWb prefetch (independent of h; LDGs fly during the poll) ----
        float xwv[2][4];
#pragma unroll
        for (int s = 0; s < 2; s++) {
            int cell = tid + s * 256;
            int b = cell >> 3, u = cell & 7;
            const float* xp = &g_XWb[((size_t)t * BB + b) * N4H + j * 8 + u];
#pragma unroll
            for (int gg = 0; gg < 4; gg++) xwv[s][gg] = xp[gg * HH];
        }

        // ---- poll A (producers published h(t) rows 0-31) + stage group A ----
        if (lane < 16) {
            int v;
            do {
                asm volatile("ld.acquire.gpu.global.s32 %0, [%1];"
                             : "=r"(v) : "l"(prod_flag) : "memory");
            } while (v < 2 * t - 1);
        }
        __syncwarp();
#pragma unroll
        for (int i = 0; i < 16; i++) {       // rows 0..31 (mb 0,1)
            int m = lane + 32 * i;
            int r = m >> 4, u16 = m & 15;
            uint32_t d = wbuf + r * 256 + ((u16 * 16) ^ ((r & 7) << 4));
            const void* s = &hsrc[(size_t)r * HH + u16 * 8];
            asm volatile("cp.async.cg.shared.global [%0], [%1], 16;\n" :: "r"(d), "l"(s));
        }
        asm volatile("cp.async.commit_group;\n" ::: "memory");

        // ---- MMA pass 0 (rows 0-31) ----
        float acc[2][4][4];
#pragma unroll
        for (int a = 0; a < 2; a++)
#pragma unroll
            for (int n = 0; n < 4; n++)
#pragma unroll
                for (int e = 0; e < 4; e++) acc[a][n][e] = 0.f;

        asm volatile("cp.async.wait_group 0;\n" ::: "memory");
        __syncwarp();
#pragma unroll
        for (int ks = 0; ks < 8; ks++) {
            const int k0 = w * 128 + ks * 16;
            uint32_t b0[4], b1[4];
#pragma unroll
            for (int nb = 0; nb < 4; nb++) {
                const __half* bp = &Wh_s[(nb * 8 + g) * 1032 + k0 + 2 * tig];
                b0[nb] = *(const uint32_t*)bp;
                b1[nb] = *(const uint32_t*)(bp + 8);
            }
#pragma unroll
            for (int mbl = 0; mbl < 2; mbl++) {
                const int r = r15 + mbl * 16;
                uint32_t addr = wbuf + r * 256 + ((ks * 32 + hi16) ^ ((r & 7) << 4));
                uint32_t a0, a1, a2, a3;
                ldsm4(a0, a1, a2, a3, addr);
#pragma unroll
                for (int nb = 0; nb < 4; nb++)
                    mma16816(acc[mbl][nb], a0, a1, a2, a3, b0[nb], b1[nb]);
            }
        }

        // ---- poll B + stage group B (transfer flies during merge0/gates0) ----
        if (lane < 16) {
            int v;
            do {
                asm volatile("ld.acquire.gpu.global.s32 %0, [%1];"
                             : "=r"(v) : "l"(prod_flag) : "memory");
            } while (v < 2 * t);
        }
        __syncwarp();
#pragma unroll
        for (int i = 16; i < 32; i++) {      // rows 32..63 (mb 2,3)
            int m = lane + 32 * i;
            int r = m >> 4, u16 = m & 15;
            uint32_t d = wbuf + r * 256 + ((u16 * 16) ^ ((r & 7) << 4));
            const void* s = &hsrc[(size_t)r * HH + u16 * 8];
            asm volatile("cp.async.cg.shared.global [%0], [%1], 16;\n" :: "r"(d), "l"(s));
        }
        asm volatile("cp.async.commit_group;\n" ::: "memory");

        // ---- merge0 + gates rows 0-31 + release 2t+1 ----
        float* zc = zs + copy * 2048;
        if (w >= 4) {
#pragma unroll
            for (int mbl = 0; mbl < 2; mbl++)
#pragma unroll
                for (int nb = 0; nb < 4; nb++) {
                    int b0r = mbl * 16 + g;
                    int u = 2 * tig;
                    *(float2*)&zc[nb * 512 + b0r * 8 + u] =
                        make_float2(acc[mbl][nb][0], acc[mbl][nb][1]);
                    *(float2*)&zc[nb * 512 + (b0r + 8) * 8 + u] =
                        make_float2(acc[mbl][nb][2], acc[mbl][nb][3]);
                }
            asm volatile("bar.sync %0, 64;" :: "r"(copy + 1) : "memory");
        } else {
            asm volatile("bar.sync %0, 64;" :: "r"(copy + 1) : "memory");
#pragma unroll
            for (int mbl = 0; mbl < 2; mbl++)
#pragma unroll
                for (int nb = 0; nb < 4; nb++) {
                    int b0r = mbl * 16 + g;
                    int u = 2 * tig;
                    float2 p0 = *(const float2*)&zc[nb * 512 + b0r * 8 + u];
                    float2 p1 = *(const float2*)&zc[nb * 512 + (b0r + 8) * 8 + u];
                    *(float2*)&zc[nb * 512 + b0r * 8 + u] =
                        make_float2(acc[mbl][nb][0] + p0.x, acc[mbl][nb][1] + p0.y);
                    *(float2*)&zc[nb * 512 + (b0r + 8) * 8 + u] =
                        make_float2(acc[mbl][nb][2] + p1.x, acc[mbl][nb][3] + p1.y);
                }
        }
        __syncthreads();

        float nh0 = 0.f; bool act0 = false;
        {
            int cell = tid;                   // rows 0-31
            int b = cell >> 3, u = cell & 7;
            int unit = j * 8 + u;
            float zi = zs[cell]        + zs[2048 + cell]
                     + zs[4096 + cell] + zs[6144 + cell] + xwv[0][0];
            float zj = zs[512 + cell]  + zs[2560 + cell]
                     + zs[4608 + cell] + zs[6656 + cell] + xwv[0][1];
            float zf = zs[1024 + cell] + zs[3072 + cell]
                     + zs[5120 + cell] + zs[7168 + cell] + xwv[0][2];
            float zo = zs[1536 + cell] + zs[3584 + cell]
                     + zs[5632 + cell] + zs[7680 + cell] + xwv[0][3];
            float nc = cst[0] * sigm(zf + 1.0f) + sigm(zi) * tanhf(zj);
            float nh = tanhf(nc) * sigm(zo);
            act0 = t < slr[0];
            __half hp = h_read[b * HH + unit];
            h_write[b * HH + unit] = act0 ? __float2half(nh) : hp;
            if (act0) cst[0] = nc;
            nh0 = nh;
        }
        __syncthreads();   // rows 0-31 of h_write visible CTA-wide before release
        if (tid == 0)
            asm volatile("st.release.gpu.global.s32 [%0], %1;"
                         :: "l"(my_flag), "r"(2 * t + 1) : "memory");
        if (act0)
            out[(tid >> 3) * HH + j * 8 + (tid & 7)] = nh0;

        // ---- MMA pass 1 (rows 32-63) ----
#pragma unroll
        for (int a = 0; a < 2; a++)
#pragma unroll
            for (int n = 0; n < 4; n++)
#pragma unroll
                for (int e = 0; e < 4; e++) acc[a][n][e] = 0.f;

        asm volatile("cp.async.wait_group 0;\n" ::: "memory");
        __syncwarp();
#pragma unroll
        for (int ks = 0; ks < 8; ks++) {
            const int k0 = w * 128 + ks * 16;
            uint32_t b0[4], b1[4];
#pragma unroll
            for (int nb = 0; nb < 4; nb++) {
                const __half* bp = &Wh_s[(nb * 8 + g) * 1032 + k0 + 2 * tig];
                b0[nb] = *(const uint32_t*)bp;
                b1[nb] = *(const uint32_t*)(bp + 8);
            }
#pragma unroll
            for (int mbl = 0; mbl < 2; mbl++) {
                const int r = r15 + (mbl + 2) * 16;
                uint32_t addr = wbuf + r * 256 + ((ks * 32 + hi16) ^ ((r & 7) << 4));
                uint32_t a0, a1, a2, a3;
                ldsm4(a0, a1, a2, a3, addr);
#pragma unroll
                for (int nb = 0; nb < 4; nb++)
                    mma16816(acc[mbl][nb], a0, a1, a2, a3, b0[nb], b1[nb]);
            }
        }

        // ---- merge1 + gates rows 32-63 + release 2t+2 ----
        if (w >= 4) {
#pragma unroll
            for (int mbl = 0; mbl < 2; mbl++)
#pragma unroll
                for (int nb = 0; nb < 4; nb++) {
                    int b0r = (mbl + 2) * 16 + g;
                    int u = 2 * tig;
                    *(float2*)&zc[nb * 512 + b0r * 8 + u] =
                        make_float2(acc[mbl][nb][0], acc[mbl][nb][1]);
                    *(float2*)&zc[nb * 512 + (b0r + 8) * 8 + u] =
                        make_float2(acc[mbl][nb][2], acc[mbl][nb][3]);
                }
            asm volatile("bar.sync %0, 64;" :: "r"(copy + 1) : "memory");
        } else {
            asm volatile("bar.sync %0, 64;" :: "r"(copy + 1) : "memory");
#pragma unroll
            for (int mbl = 0; mbl < 2; mbl++)
#pragma unroll
                for (int nb = 0; nb < 4; nb++) {
                    int b0r = (mbl + 2) * 16 + g;
                    int u = 2 * tig;
                    float2 p0 = *(const float2*)&zc[nb * 512 + b0r * 8 + u];
                    float2 p1 = *(const float2*)&zc[nb * 512 + (b0r + 8) * 8 + u];
                    *(float2*)&zc[nb * 512 + b0r * 8 + u] =
                        make_float2(acc[mbl][nb][0] + p0.x, acc[mbl][nb][1] + p0.y);
                    *(float2*)&zc[nb * 512 + (b0r + 8) * 8 + u] =
                        make_float2(acc[mbl][nb][2] + p1.x, acc[mbl][nb][3] + p1.y);
                }
        }
        __syncthreads();

        float nh1 = 0.f; bool act1 = false;
        {
            int cell = tid + 256;             // rows 32-63
            int b = cell >> 3, u = cell & 7;
            int unit = j * 8 + u;
            float zi = zs[cell]        + zs[2048 + cell]
                     + zs[4096 + cell] + zs[6144 + cell] + xwv[1][0];
            float zj = zs[512 + cell]  + zs[2560 + cell]
                     + zs[4608 + cell] + zs[6656 + cell] + xwv[1][1];
            float zf = zs[1024 + cell] + zs[3072 + cell]
                     + zs[5120 + cell] + zs[7168 + cell] + xwv[1][2];
            float zo = zs[1536 + cell] + zs[3584 + cell]
                     + zs[5632 + cell] + zs[7680 + cell] + xwv[1][3];
            float nc = cst[1] * sigm(zf + 1.0f) + sigm(zi) * tanhf(zj);
            float nh = tanhf(nc) * sigm(zo);
            act1 = t < slr[1];
            __half hp = h_read[b * HH + unit];
            h_write[b * HH + unit] = act1 ? __float2half(nh) : hp;
            if (act1) cst[1] = nc;
            nh1 = nh;
        }
        __syncthreads();   // rows 32-63 of h_write visible before release
        if (tid == 0)
            asm volatile("st.release.gpu.global.s32 [%0], %1;"
                         :: "l"(my_flag), "r"(2 * t + 2) : "memory");
        if (act1)
            out[((tid + 256) >> 3) * HH + j * 8 + (tid & 7)] = nh1;
    }
}

// ---------------- launch ----------------
extern "C" void kernel_launch(void* const* d_in, const int* in_sizes, int n_in,
                              void* d_out, int out_size) {
    const float* x = (const float*)d_in[0];
    const int* seq_len = (const int*)d_in[1];
    const float* W = (const float*)d_in[2];
    const float* bias = (const float*)d_in[3];
    float* out = (float*)d_out;

    cudaFuncSetAttribute(lstm_persistent_kernel,
                         cudaFuncAttributeMaxDynamicSharedMemorySize, SM_TOT);

    noop_kernel<<<1, 32>>>();   // keeps lstm at global launch #6 for ncu
    prep_kernel<<<8192, 256>>>(x, W, out);
    gemm_x_kernel<<<dim3(N4H / 64, MM / 64), 128>>>(bias);
    lstm_persistent_kernel<<<GRID, 256, SM_TOT>>>(seq_len, out);
}

// round 16
// speedup vs baseline: 1.0085x; 1.0085x over previous
#include <cuda_runtime.h>
#include <cuda_fp16.h>
#include <cstdint>

// Problem constants
#define BB 64
#define TT 256
#define DD 512
#define HH 1024
#define N4H 4096   // 4*H
#define MM (BB*TT) // 16384
#define GRID 128   // persistent CTAs (co-resident)

// ---------------- device scratch ----------------
__device__ __half g_x16[(size_t)MM * DD];
__device__ __half g_WxT[(size_t)N4H * DD];
__device__ __half g_WhT[(size_t)N4H * HH];
__device__ float  g_XWb[(size_t)MM * N4H];   // layout [T][B][4H]
__device__ __half g_h16[2][BB * HH];
__device__ int    g_flags[GRID * 32];        // 128B-padded per-CTA "steps done" flags

// ---------------- helpers ----------------
__device__ __forceinline__ float sigm(float x) { return 1.f / (1.f + __expf(-x)); }

__device__ __forceinline__ void mma16816(float* c,
                                         uint32_t a0, uint32_t a1, uint32_t a2, uint32_t a3,
                                         uint32_t b0, uint32_t b1) {
    asm volatile(
        "mma.sync.aligned.m16n8k16.row.col.f32.f16.f16.f32 "
        "{%0,%1,%2,%3}, {%4,%5,%6,%7}, {%8,%9}, {%0,%1,%2,%3};\n"
        : "+f"(c[0]), "+f"(c[1]), "+f"(c[2]), "+f"(c[3])
        : "r"(a0), "r"(a1), "r"(a2), "r"(a3), "r"(b0), "r"(b1));
}

__device__ __forceinline__ void ldsm4(uint32_t& r0, uint32_t& r1, uint32_t& r2, uint32_t& r3,
                                      uint32_t addr) {
    asm volatile("ldmatrix.sync.aligned.m8n8.x4.shared.b16 {%0,%1,%2,%3}, [%4];"
                 : "=r"(r0), "=r"(r1), "=r"(r2), "=r"(r3) : "r"(addr));
}

// ---------------- dummy (ncu alignment: lstm = global launch #6) -------------
__global__ void noop_kernel() {}

// ---------------- prep ----------------
__global__ void prep_kernel(const float* __restrict__ x,
                            const float* __restrict__ W,
                            float* __restrict__ out) {
    size_t i0 = (size_t)blockIdx.x * blockDim.x + threadIdx.x;
    size_t stride = (size_t)gridDim.x * blockDim.x;
    for (size_t i = i0; i < GRID * 32; i += stride)
        g_flags[i] = 0;
    for (size_t i = i0; i < (size_t)MM * DD; i += stride)
        g_x16[i] = __float2half(x[i]);
    for (size_t i = i0; i < (size_t)N4H * DD; i += stride) {
        size_t n = i >> 9, k = i & 511;
        g_WxT[i] = __float2half(W[k * N4H + n]);
    }
    for (size_t i = i0; i < (size_t)N4H * HH; i += stride) {
        size_t n = i >> 10, k = i & 1023;
        g_WhT[i] = __float2half(W[(DD + k) * N4H + n]);
    }
    for (size_t i = i0; i < (size_t)BB * HH; i += stride) {
        out[i] = 0.f;
        g_h16[0][i] = __float2half(0.f);
        g_h16[1][i] = __float2half(0.f);
    }
}

// ---------------- precompute XWb = x @ Wx + b, output [T][B][4H] --------------
// 128x128 CTA tile, 256 threads / 8 warps (warp = 32 rows x 64 cols), K-chunks
// of 64 with double-buffered cp.async. Halves L2 traffic vs 64x64 tiles.
#define GX_BUF 18432   // 128*72*2 bytes per As/Bs buffer

__global__ __launch_bounds__(256) void gemm_x_kernel(const float* __restrict__ bias) {
    extern __shared__ char gx_smem[];
    __half* As = (__half*)gx_smem;                 // 2 buffers of 128x72
    __half* Bs = (__half*)(gx_smem + 2 * GX_BUF);  // 2 buffers of 128x72
    const int tid = threadIdx.x;
    const int w = tid >> 5, lane = tid & 31;
    const int wm = w & 3, wn = w >> 2;             // warp tile: rows 32wm, cols 64wn
    const int g = lane >> 2, tig = lane & 3;
    const int mt = blockIdx.y, nt = blockIdx.x;
    const int mbase = mt * 128;
    const int nbase = nt * 128;

    const uint32_t AsS = (uint32_t)__cvta_generic_to_shared(As);
    const uint32_t BsS = (uint32_t)__cvta_generic_to_shared(Bs);
    const int aoff = (lane & 15) * 144 + ((lane >> 4) << 4);
    const int boff = ((lane & 7) + ((lane >> 4) & 1) * 8) * 144 + ((lane >> 3) & 1) * 16;

    float acc[2][8][4];
#pragma unroll
    for (int a = 0; a < 2; a++)
#pragma unroll
        for (int n = 0; n < 8; n++)
#pragma unroll
            for (int e = 0; e < 4; e++) acc[a][n][e] = 0.f;

    auto stage = [&](int c, int buf) {
        int kc = c * 64;
#pragma unroll
        for (int i = 0; i < 4; i++) {
            int idx = tid + i * 256;               // 0..1023
            int r = idx >> 3, c8 = idx & 7;
            uint32_t da = (uint32_t)__cvta_generic_to_shared(&As[buf * 9216 + r * 72 + c8 * 8]);
            const void* sa = &g_x16[(size_t)(mbase + r) * DD + kc + c8 * 8];
            asm volatile("cp.async.cg.shared.global [%0], [%1], 16;\n" :: "r"(da), "l"(sa));
            uint32_t db = (uint32_t)__cvta_generic_to_shared(&Bs[buf * 9216 + r * 72 + c8 * 8]);
            const void* sb = &g_WxT[(size_t)(nbase + r) * DD + kc + c8 * 8];
            asm volatile("cp.async.cg.shared.global [%0], [%1], 16;\n" :: "r"(db), "l"(sb));
        }
        asm volatile("cp.async.commit_group;\n" ::: "memory");
    };

    stage(0, 0);
    for (int c = 0; c < 8; c++) {
        __syncthreads();
        if (c < 7) {
            stage(c + 1, (c + 1) & 1);
            asm volatile("cp.async.wait_group 1;\n" ::: "memory");
        } else {
            asm volatile("cp.async.wait_group 0;\n" ::: "memory");
        }
        __syncthreads();   // chunk c fully staged by all threads
        const uint32_t Ab = AsS + (c & 1) * GX_BUF;
        const uint32_t Bb = BsS + (c & 1) * GX_BUF;
#pragma unroll
        for (int k0 = 0; k0 < 64; k0 += 16) {
            // B fragments: 4 ldsm4 -> 8 n-frags of 8 cols
            uint32_t bf[8][2];
#pragma unroll
            for (int nb2 = 0; nb2 < 4; nb2++) {
                uint32_t b0, b1, b2, b3;
                ldsm4(b0, b1, b2, b3,
                      Bb + (wn * 64 + nb2 * 16) * 144 + k0 * 2 + boff);
                bf[nb2 * 2][0] = b0; bf[nb2 * 2][1] = b1;
                bf[nb2 * 2 + 1][0] = b2; bf[nb2 * 2 + 1][1] = b3;
            }
#pragma unroll
            for (int mf = 0; mf < 2; mf++) {
                uint32_t a0, a1, a2, a3;
                ldsm4(a0, a1, a2, a3,
                      Ab + (wm * 32 + mf * 16) * 144 + k0 * 2 + aoff);
#pragma unroll
                for (int nb = 0; nb < 8; nb++)
                    mma16816(acc[mf][nb], a0, a1, a2, a3, bf[nb][0], bf[nb][1]);
            }
        }
    }

    // epilogue: add bias, scatter to [T][B][4H] (m = b*TT + t -> row t*BB + b)
#pragma unroll
    for (int mf = 0; mf < 2; mf++) {
#pragma unroll
        for (int nb = 0; nb < 8; nb++) {
            int col = nbase + wn * 64 + nb * 8 + 2 * tig;
            float2 bv = *(const float2*)&bias[col];
            int m0 = mbase + wm * 32 + mf * 16 + g;
            int m1 = m0 + 8;
            size_t r0 = (size_t)((m0 & 255) * BB + (m0 >> 8));
            size_t r1 = (size_t)((m1 & 255) * BB + (m1 >> 8));
            float2 v0 = {acc[mf][nb][0] + bv.x, acc[mf][nb][1] + bv.y};
            float2 v1 = {acc[mf][nb][2] + bv.x, acc[mf][nb][3] + bv.y};
            *(float2*)&g_XWb[r0 * N4H + col] = v0;
            *(float2*)&g_XWb[r1 * N4H + col] = v1;
        }
    }
}

// ---------------- persistent LSTM recurrence: k-partitioned warps + dataflow --
// (R14 version — best passing at 1476 us.)
// Warp w owns k-eighth [128w,128w+128) = h units from producer CTAs [16w,16w+16).
// SMEM: Wh_s 32 x 1032 halves (66048) | Hs 8 x 16384 (131072, XOR-swizzled)
//       zs 4 x 2048 f32 (32768)  -> total 229888 B
#define SM_WH   0
#define SM_HS   66048
#define SM_ZS   197120
#define SM_TOT  229888

__global__ __launch_bounds__(256, 1) void lstm_persistent_kernel(
        const int* __restrict__ seq_len, float* __restrict__ out) {
    extern __shared__ char smem_raw[];
    __half* Wh_s = (__half*)(smem_raw + SM_WH);
    float*  zs   = (float*)(smem_raw + SM_ZS);

    const int tid = threadIdx.x;
    const int w = tid >> 5, lane = tid & 31;
    const int g = lane >> 2, tig = lane & 3;
    const int j = blockIdx.x;                 // owns hidden units [8j, 8j+8)
    const int r15 = lane & 15;
    const int hi16 = (lane >> 4) << 4;        // 0 or 16 (k vs k+8 halves)
    const int copy = w & 3;                   // zs copy / pair id

    const uint32_t wbuf = (uint32_t)__cvta_generic_to_shared(smem_raw + SM_HS) + w * 16384;

    // Load Wh slice: 32 local cols (gate*8+unit), padded stride 1032 halves
    for (int idx = tid; idx < 4096; idx += 256) {
        int lc = idx >> 7;
        int kk = (idx & 127) * 8;
        int gg = lc >> 3, u = lc & 7;
        size_t gcol = (size_t)gg * HH + j * 8 + u;
        *(int4*)&Wh_s[lc * 1032 + kk] = *(const int4*)&g_WhT[gcol * HH + kk];
    }
    float cst[2] = {0.f, 0.f};
    int slr[2];
#pragma unroll
    for (int s = 0; s < 2; s++) slr[s] = seq_len[(tid + s * 256) >> 3];
    int* my_flag = &g_flags[j * 32];
    int* prod_flag = (lane < 16) ? &g_flags[(w * 16 + lane) * 32] : nullptr;
    __syncthreads();

    for (int t = 0; t < TT; t++) {
        const __half* __restrict__ h_read = g_h16[t & 1];
        __half* __restrict__ h_write = g_h16[(t + 1) & 1];
        const __half* __restrict__ hsrc = h_read + w * 128;  // this warp's k-eighth

        // ---- XWb prefetch first (independent of h: LDGs fly during the poll)
        float xwv[2][4];
#pragma unroll
        for (int s = 0; s < 2; s++) {
            int cell = tid + s * 256;
            int b = cell >> 3, u = cell & 7;
            const float* xp = &g_XWb[((size_t)t * BB + b) * N4H + j * 8 + u];
#pragma unroll
            for (int gg = 0; gg < 4; gg++) xwv[s][gg] = xp[gg * HH];
        }

        // ---- per-warp producer poll: wait until 16 producers published step t
        if (lane < 16) {
            int v;
            do {
                asm volatile("ld.acquire.gpu.global.s32 %0, [%1];"
                             : "=r"(v) : "l"(prod_flag) : "memory");
            } while (v < t);
        }
        __syncwarp();

        // ---- stage own eighth: 64 rows x 256 B, XOR-swizzled, 2 groups ----
#pragma unroll
        for (int i = 0; i < 16; i++) {       // group A: rows 0..31 (mb 0,1)
            int m = lane + 32 * i;
            int r = m >> 4, u16 = m & 15;
            uint32_t d = wbuf + r * 256 + ((u16 * 16) ^ ((r & 7) << 4));
            const void* s = &hsrc[(size_t)r * HH + u16 * 8];
            asm volatile("cp.async.cg.shared.global [%0], [%1], 16;\n" :: "r"(d), "l"(s));
        }
        asm volatile("cp.async.commit_group;\n" ::: "memory");
#pragma unroll
        for (int i = 16; i < 32; i++) {      // group B: rows 32..63 (mb 2,3)
            int m = lane + 32 * i;
            int r = m >> 4, u16 = m & 15;
            uint32_t d = wbuf + r * 256 + ((u16 * 16) ^ ((r & 7) << 4));
            const void* s = &hsrc[(size_t)r * HH + u16 * 8];
            asm volatile("cp.async.cg.shared.global [%0], [%1], 16;\n" :: "r"(d), "l"(s));
        }
        asm volatile("cp.async.commit_group;\n" ::: "memory");

        // ---- MMA: 8 ksteps x 4 gates x 4 mb, two row-half passes ----
        float acc[4][4][4];
#pragma unroll
        for (int a = 0; a < 4; a++)
#pragma unroll
            for (int n = 0; n < 4; n++)
#pragma unroll
                for (int e = 0; e < 4; e++) acc[a][n][e] = 0.f;

#pragma unroll
        for (int pass = 0; pass < 2; pass++) {
            if (pass == 0)
                asm volatile("cp.async.wait_group 1;\n" ::: "memory");
            else
                asm volatile("cp.async.wait_group 0;\n" ::: "memory");
            __syncwarp();
#pragma unroll
            for (int ks = 0; ks < 8; ks++) {
                const int k0 = w * 128 + ks * 16;       // global k (B index)
                uint32_t b0[4], b1[4];
#pragma unroll
                for (int nb = 0; nb < 4; nb++) {
                    const __half* bp = &Wh_s[(nb * 8 + g) * 1032 + k0 + 2 * tig];
                    b0[nb] = *(const uint32_t*)bp;
                    b1[nb] = *(const uint32_t*)(bp + 8);
                }
#pragma unroll
                for (int mbl = 0; mbl < 2; mbl++) {
                    const int mb = pass * 2 + mbl;
                    const int r = r15 + mb * 16;
                    uint32_t addr = wbuf + r * 256 + ((ks * 32 + hi16) ^ ((r & 7) << 4));
                    uint32_t a0, a1, a2, a3;
                    ldsm4(a0, a1, a2, a3, addr);
#pragma unroll
                    for (int nb = 0; nb < 4; nb++)
                        mma16816(acc[mb][nb], a0, a1, a2, a3, b0[nb], b1[nb]);
                }
            }
        }

        // ---- pairwise zs merge: warp w (>=4) writes raw, warp w-4 adds ----
        float* zc = zs + copy * 2048;
        if (w >= 4) {
#pragma unroll
            for (int mb = 0; mb < 4; mb++)
#pragma unroll
                for (int nb = 0; nb < 4; nb++) {
                    int b0r = mb * 16 + g;
                    int u = 2 * tig;
                    *(float2*)&zc[nb * 512 + b0r * 8 + u] =
                        make_float2(acc[mb][nb][0], acc[mb][nb][1]);
                    *(float2*)&zc[nb * 512 + (b0r + 8) * 8 + u] =
                        make_float2(acc[mb][nb][2], acc[mb][nb][3]);
                }
            asm volatile("bar.sync %0, 64;" :: "r"(copy + 1) : "memory");
        } else {
            asm volatile("bar.sync %0, 64;" :: "r"(copy + 1) : "memory");
#pragma unroll
            for (int mb = 0; mb < 4; mb++)
#pragma unroll
                for (int nb = 0; nb < 4; nb++) {
                    int b0r = mb * 16 + g;
                    int u = 2 * tig;
                    float2 p0 = *(const float2*)&zc[nb * 512 + b0r * 8 + u];
                    float2 p1 = *(const float2*)&zc[nb * 512 + (b0r + 8) * 8 + u];
                    *(float2*)&zc[nb * 512 + b0r * 8 + u] =
                        make_float2(acc[mb][nb][0] + p0.x, acc[mb][nb][1] + p0.y);
                    *(float2*)&zc[nb * 512 + (b0r + 8) * 8 + u] =
                        make_float2(acc[mb][nb][2] + p1.x, acc[mb][nb][3] + p1.y);
                }
        }
        __syncthreads();   // all warps' polls passed + zs merged

        // ---- gates + state update (i, j, f, o; forget bias 1.0) ----
        float nhv[2];
        bool actv[2];
#pragma unroll
        for (int s = 0; s < 2; s++) {
            int cell = tid + s * 256;
            int b = cell >> 3, u = cell & 7;
            int unit = j * 8 + u;
            float zi = zs[cell]        + zs[2048 + cell]
                     + zs[4096 + cell] + zs[6144 + cell] + xwv[s][0];
            float zj = zs[512 + cell]  + zs[2560 + cell]
                     + zs[4608 + cell] + zs[6656 + cell] + xwv[s][1];
            float zf = zs[1024 + cell] + zs[3072 + cell]
                     + zs[5120 + cell] + zs[7168 + cell] + xwv[s][2];
            float zo = zs[1536 + cell] + zs[3584 + cell]
                     + zs[5632 + cell] + zs[7680 + cell] + xwv[s][3];
            float nc = cst[s] * sigm(zf + 1.0f) + sigm(zi) * tanhf(zj);
            float nh = tanhf(nc) * sigm(zo);
            bool act = t < slr[s];
            __half hp = h_read[b * HH + unit];
            h_write[b * HH + unit] = act ? __float2half(nh) : hp;
            if (act) cst[s] = nc;
            nhv[s] = nh;
            actv[s] = act;
        }

        // ---- publish h availability (release), then off-path out stores ----
        __syncthreads();   // all threads' h_write stores happen-before release
        if (tid == 0)
            asm volatile("st.release.gpu.global.s32 [%0], %1;"
                         :: "l"(my_flag), "r"(t + 1) : "memory");
#pragma unroll
        for (int s = 0; s < 2; s++) {
            if (actv[s]) {
                int cell = tid + s * 256;
                out[(cell >> 3) * HH + j * 8 + (cell & 7)] = nhv[s];
            }
        }
    }
}

// ---------------- launch ----------------
extern "C" void kernel_launch(void* const* d_in, const int* in_sizes, int n_in,
                              void* d_out, int out_size) {
    const float* x = (const float*)d_in[0];
    const int* seq_len = (const int*)d_in[1];
    const float* W = (const float*)d_in[2];
    const float* bias = (const float*)d_in[3];
    float* out = (float*)d_out;

    cudaFuncSetAttribute(lstm_persistent_kernel,
                         cudaFuncAttributeMaxDynamicSharedMemorySize, SM_TOT);
    cudaFuncSetAttribute(gemm_x_kernel,
                         cudaFuncAttributeMaxDynamicSharedMemorySize, 4 * GX_BUF);

    noop_kernel<<<1, 32>>>();   // keeps lstm at global launch #6 for ncu
    prep_kernel<<<8192, 256>>>(x, W, out);
    gemm_x_kernel<<<dim3(N4H / 128, MM / 128), 256, 4 * GX_BUF>>>(bias);
    lstm_persistent_kernel<<<GRID, 256, SM_TOT>>>(seq_len, out);
}

// round 17
// speedup vs baseline: 1.1059x; 1.0966x over previous
#include <cuda_runtime.h>
#include <cuda_fp16.h>
#include <cstdint>

// Problem constants
#define BB 64
#define TT 256
#define DD 512
#define HH 1024
#define N4H 4096   // 4*H
#define MM (BB*TT) // 16384
#define GRID 128   // persistent CTAs (co-resident)

// ---------------- device scratch ----------------
__device__ __half g_x16[(size_t)MM * DD];
__device__ __half g_WxT[(size_t)N4H * DD];
__device__ __half g_WhT[(size_t)N4H * HH];
__device__ float  g_XWb[(size_t)MM * N4H];   // layout [T][B][4H]
__device__ __half g_h16[2][BB * HH];
__device__ int    g_flags[GRID * 32];        // 128B-padded per-CTA "steps done" flags

// ---------------- helpers ----------------
// MUFU-based fast activations (error ~1e-6, negligible vs fp16 path noise)
__device__ __forceinline__ float sigm(float x) {
    return __fdividef(1.f, 1.f + __expf(-x));
}
__device__ __forceinline__ float tanh_f(float x) {
    return 1.f - __fdividef(2.f, __expf(2.f * x) + 1.f);
}

__device__ __forceinline__ void mma16816(float* c,
                                         uint32_t a0, uint32_t a1, uint32_t a2, uint32_t a3,
                                         uint32_t b0, uint32_t b1) {
    asm volatile(
        "mma.sync.aligned.m16n8k16.row.col.f32.f16.f16.f32 "
        "{%0,%1,%2,%3}, {%4,%5,%6,%7}, {%8,%9}, {%0,%1,%2,%3};\n"
        : "+f"(c[0]), "+f"(c[1]), "+f"(c[2]), "+f"(c[3])
        : "r"(a0), "r"(a1), "r"(a2), "r"(a3), "r"(b0), "r"(b1));
}

__device__ __forceinline__ void ldsm4(uint32_t& r0, uint32_t& r1, uint32_t& r2, uint32_t& r3,
                                      uint32_t addr) {
    asm volatile("ldmatrix.sync.aligned.m8n8.x4.shared.b16 {%0,%1,%2,%3}, [%4];"
                 : "=r"(r0), "=r"(r1), "=r"(r2), "=r"(r3) : "r"(addr));
}

// ---------------- dummy (ncu alignment: lstm = global launch #6) -------------
__global__ void noop_kernel() {}

// ---------------- prep ----------------
__global__ void prep_kernel(const float* __restrict__ x,
                            const float* __restrict__ W,
                            float* __restrict__ out) {
    size_t i0 = (size_t)blockIdx.x * blockDim.x + threadIdx.x;
    size_t stride = (size_t)gridDim.x * blockDim.x;
    for (size_t i = i0; i < GRID * 32; i += stride)
        g_flags[i] = 0;
    for (size_t i = i0; i < (size_t)MM * DD; i += stride)
        g_x16[i] = __float2half(x[i]);
    for (size_t i = i0; i < (size_t)N4H * DD; i += stride) {
        size_t n = i >> 9, k = i & 511;
        g_WxT[i] = __float2half(W[k * N4H + n]);
    }
    for (size_t i = i0; i < (size_t)N4H * HH; i += stride) {
        size_t n = i >> 10, k = i & 1023;
        g_WhT[i] = __float2half(W[(DD + k) * N4H + n]);
    }
    for (size_t i = i0; i < (size_t)BB * HH; i += stride) {
        out[i] = 0.f;
        g_h16[0][i] = __float2half(0.f);
        g_h16[1][i] = __float2half(0.f);
    }
}

// ---------------- precompute XWb = x @ Wx + b, output [T][B][4H] --------------
// 128x128 CTA tile, 256 threads / 8 warps, double-buffered cp.async.
#define GX_BUF 18432   // 128*72*2 bytes per As/Bs buffer

__global__ __launch_bounds__(256) void gemm_x_kernel(const float* __restrict__ bias) {
    extern __shared__ char gx_smem[];
    __half* As = (__half*)gx_smem;                 // 2 buffers of 128x72
    __half* Bs = (__half*)(gx_smem + 2 * GX_BUF);  // 2 buffers of 128x72
    const int tid = threadIdx.x;
    const int w = tid >> 5, lane = tid & 31;
    const int wm = w & 3, wn = w >> 2;             // warp tile: rows 32wm, cols 64wn
    const int g = lane >> 2, tig = lane & 3;
    const int mt = blockIdx.y, nt = blockIdx.x;
    const int mbase = mt * 128;
    const int nbase = nt * 128;

    const uint32_t AsS = (uint32_t)__cvta_generic_to_shared(As);
    const uint32_t BsS = (uint32_t)__cvta_generic_to_shared(Bs);
    const int aoff = (lane & 15) * 144 + ((lane >> 4) << 4);
    const int boff = ((lane & 7) + ((lane >> 4) & 1) * 8) * 144 + ((lane >> 3) & 1) * 16;

    float acc[2][8][4];
#pragma unroll
    for (int a = 0; a < 2; a++)
#pragma unroll
        for (int n = 0; n < 8; n++)
#pragma unroll
            for (int e = 0; e < 4; e++) acc[a][n][e] = 0.f;

    auto stage = [&](int c, int buf) {
        int kc = c * 64;
#pragma unroll
        for (int i = 0; i < 4; i++) {
            int idx = tid + i * 256;               // 0..1023
            int r = idx >> 3, c8 = idx & 7;
            uint32_t da = (uint32_t)__cvta_generic_to_shared(&As[buf * 9216 + r * 72 + c8 * 8]);
            const void* sa = &g_x16[(size_t)(mbase + r) * DD + kc + c8 * 8];
            asm volatile("cp.async.cg.shared.global [%0], [%1], 16;\n" :: "r"(da), "l"(sa));
            uint32_t db = (uint32_t)__cvta_generic_to_shared(&Bs[buf * 9216 + r * 72 + c8 * 8]);
            const void* sb = &g_WxT[(size_t)(nbase + r) * DD + kc + c8 * 8];
            asm volatile("cp.async.cg.shared.global [%0], [%1], 16;\n" :: "r"(db), "l"(sb));
        }
        asm volatile("cp.async.commit_group;\n" ::: "memory");
    };

    stage(0, 0);
    for (int c = 0; c < 8; c++) {
        __syncthreads();
        if (c < 7) {
            stage(c + 1, (c + 1) & 1);
            asm volatile("cp.async.wait_group 1;\n" ::: "memory");
        } else {
            asm volatile("cp.async.wait_group 0;\n" ::: "memory");
        }
        __syncthreads();   // chunk c fully staged by all threads
        const uint32_t Ab = AsS + (c & 1) * GX_BUF;
        const uint32_t Bb = BsS + (c & 1) * GX_BUF;
#pragma unroll
        for (int k0 = 0; k0 < 64; k0 += 16) {
            uint32_t bf[8][2];
#pragma unroll
            for (int nb2 = 0; nb2 < 4; nb2++) {
                uint32_t b0, b1, b2, b3;
                ldsm4(b0, b1, b2, b3,
                      Bb + (wn * 64 + nb2 * 16) * 144 + k0 * 2 + boff);
                bf[nb2 * 2][0] = b0; bf[nb2 * 2][1] = b1;
                bf[nb2 * 2 + 1][0] = b2; bf[nb2 * 2 + 1][1] = b3;
            }
#pragma unroll
            for (int mf = 0; mf < 2; mf++) {
                uint32_t a0, a1, a2, a3;
                ldsm4(a0, a1, a2, a3,
                      Ab + (wm * 32 + mf * 16) * 144 + k0 * 2 + aoff);
#pragma unroll
                for (int nb = 0; nb < 8; nb++)
                    mma16816(acc[mf][nb], a0, a1, a2, a3, bf[nb][0], bf[nb][1]);
            }
        }
    }

    // epilogue: add bias, scatter to [T][B][4H] (m = b*TT + t -> row t*BB + b)
#pragma unroll
    for (int mf = 0; mf < 2; mf++) {
#pragma unroll
        for (int nb = 0; nb < 8; nb++) {
            int col = nbase + wn * 64 + nb * 8 + 2 * tig;
            float2 bv = *(const float2*)&bias[col];
            int m0 = mbase + wm * 32 + mf * 16 + g;
            int m1 = m0 + 8;
            size_t r0 = (size_t)((m0 & 255) * BB + (m0 >> 8));
            size_t r1 = (size_t)((m1 & 255) * BB + (m1 >> 8));
            float2 v0 = {acc[mf][nb][0] + bv.x, acc[mf][nb][1] + bv.y};
            float2 v1 = {acc[mf][nb][2] + bv.x, acc[mf][nb][3] + bv.y};
            *(float2*)&g_XWb[r0 * N4H + col] = v0;
            *(float2*)&g_XWb[r1 * N4H + col] = v1;
        }
    }
}

// ---------------- persistent LSTM recurrence: k-partitioned warps + dataflow --
// Warp w owns k-eighth [128w,128w+128) = h units from producer CTAs [16w,16w+16).
// SMEM: Wh_s 32 x 1032 halves (66048) | Hs 8 x 16384 (131072, XOR-swizzled)
//       zs 4 x 2048 f32 (32768)  -> total 229888 B
#define SM_WH   0
#define SM_HS   66048
#define SM_ZS   197120
#define SM_TOT  229888

__global__ __launch_bounds__(256, 1) void lstm_persistent_kernel(
        const int* __restrict__ seq_len, float* __restrict__ out) {
    extern __shared__ char smem_raw[];
    __half* Wh_s = (__half*)(smem_raw + SM_WH);
    float*  zs   = (float*)(smem_raw + SM_ZS);

    const int tid = threadIdx.x;
    const int w = tid >> 5, lane = tid & 31;
    const int g = lane >> 2, tig = lane & 3;
    const int j = blockIdx.x;                 // owns hidden units [8j, 8j+8)
    const int r15 = lane & 15;
    const int hi16 = (lane >> 4) << 4;        // 0 or 16 (k vs k+8 halves)
    const int copy = w & 3;                   // zs copy / pair id

    const uint32_t wbuf = (uint32_t)__cvta_generic_to_shared(smem_raw + SM_HS) + w * 16384;

    // Load Wh slice: 32 local cols (gate*8+unit), padded stride 1032 halves
    for (int idx = tid; idx < 4096; idx += 256) {
        int lc = idx >> 7;
        int kk = (idx & 127) * 8;
        int gg = lc >> 3, u = lc & 7;
        size_t gcol = (size_t)gg * HH + j * 8 + u;
        *(int4*)&Wh_s[lc * 1032 + kk] = *(const int4*)&g_WhT[gcol * HH + kk];
    }
    // per-thread state: cell c, carried h (fp32; re-rounded store is bit-stable)
    float cst[2] = {0.f, 0.f};
    float hcur[2] = {0.f, 0.f};
    int slr[2];
#pragma unroll
    for (int s = 0; s < 2; s++) slr[s] = seq_len[(tid + s * 256) >> 3];
    int* my_flag = &g_flags[j * 32];
    int* prod_flag = (lane < 16) ? &g_flags[(w * 16 + lane) * 32] : nullptr;
    __syncthreads();

    for (int t = 0; t < TT; t++) {
        const __half* __restrict__ h_read = g_h16[t & 1];
        __half* __restrict__ h_write = g_h16[(t + 1) & 1];
        const __half* __restrict__ hsrc = h_read + w * 128;  // this warp's k-eighth

        // ---- XWb prefetch first (independent of h: LDGs fly during the poll)
        float xwv[2][4];
#pragma unroll
        for (int s = 0; s < 2; s++) {
            int cell = tid + s * 256;
            int b = cell >> 3, u = cell & 7;
            const float* xp = &g_XWb[((size_t)t * BB + b) * N4H + j * 8 + u];
#pragma unroll
            for (int gg = 0; gg < 4; gg++) xwv[s][gg] = xp[gg * HH];
        }

        // ---- per-warp producer poll: wait until 16 producers published step t
        if (lane < 16) {
            int v;
            do {
                asm volatile("ld.acquire.gpu.global.s32 %0, [%1];"
                             : "=r"(v) : "l"(prod_flag) : "memory");
            } while (v < t);
        }
        __syncwarp();

        // ---- stage own eighth: 64 rows x 256 B, XOR-swizzled, 2 groups ----
#pragma unroll
        for (int i = 0; i < 16; i++) {       // group A: rows 0..31 (mb 0,1)
            int m = lane + 32 * i;
            int r = m >> 4, u16 = m & 15;
            uint32_t d = wbuf + r * 256 + ((u16 * 16) ^ ((r & 7) << 4));
            const void* s = &hsrc[(size_t)r * HH + u16 * 8];
            asm volatile("cp.async.cg.shared.global [%0], [%1], 16;\n" :: "r"(d), "l"(s));
        }
        asm volatile("cp.async.commit_group;\n" ::: "memory");
#pragma unroll
        for (int i = 16; i < 32; i++) {      // group B: rows 32..63 (mb 2,3)
            int m = lane + 32 * i;
            int r = m >> 4, u16 = m & 15;
            uint32_t d = wbuf + r * 256 + ((u16 * 16) ^ ((r & 7) << 4));
            const void* s = &hsrc[(size_t)r * HH + u16 * 8];
            asm volatile("cp.async.cg.shared.global [%0], [%1], 16;\n" :: "r"(d), "l"(s));
        }
        asm volatile("cp.async.commit_group;\n" ::: "memory");

        // ---- MMA: 8 ksteps x 4 gates x 4 mb, two row-half passes ----
        float acc[4][4][4];
#pragma unroll
        for (int a = 0; a < 4; a++)
#pragma unroll
            for (int n = 0; n < 4; n++)
#pragma unroll
                for (int e = 0; e < 4; e++) acc[a][n][e] = 0.f;

#pragma unroll
        for (int pass = 0; pass < 2; pass++) {
            if (pass == 0)
                asm volatile("cp.async.wait_group 1;\n" ::: "memory");
            else
                asm volatile("cp.async.wait_group 0;\n" ::: "memory");
            __syncwarp();
#pragma unroll
            for (int ks = 0; ks < 8; ks++) {
                const int k0 = w * 128 + ks * 16;       // global k (B index)
                uint32_t b0[4], b1[4];
#pragma unroll
                for (int nb = 0; nb < 4; nb++) {
                    const __half* bp = &Wh_s[(nb * 8 + g) * 1032 + k0 + 2 * tig];
                    b0[nb] = *(const uint32_t*)bp;
                    b1[nb] = *(const uint32_t*)(bp + 8);
                }
#pragma unroll
                for (int mbl = 0; mbl < 2; mbl++) {
                    const int mb = pass * 2 + mbl;
                    const int r = r15 + mb * 16;
                    uint32_t addr = wbuf + r * 256 + ((ks * 32 + hi16) ^ ((r & 7) << 4));
                    uint32_t a0, a1, a2, a3;
                    ldsm4(a0, a1, a2, a3, addr);
#pragma unroll
                    for (int nb = 0; nb < 4; nb++)
                        mma16816(acc[mb][nb], a0, a1, a2, a3, b0[nb], b1[nb]);
                }
            }
        }

        // ---- pairwise zs merge: warp w (>=4) writes raw, warp w-4 adds ----
        float* zc = zs + copy * 2048;
        if (w >= 4) {
#pragma unroll
            for (int mb = 0; mb < 4; mb++)
#pragma unroll
                for (int nb = 0; nb < 4; nb++) {
                    int b0r = mb * 16 + g;
                    int u = 2 * tig;
                    *(float2*)&zc[nb * 512 + b0r * 8 + u] =
                        make_float2(acc[mb][nb][0], acc[mb][nb][1]);
                    *(float2*)&zc[nb * 512 + (b0r + 8) * 8 + u] =
                        make_float2(acc[mb][nb][2], acc[mb][nb][3]);
                }
            asm volatile("bar.sync %0, 64;" :: "r"(copy + 1) : "memory");
        } else {
            asm volatile("bar.sync %0, 64;" :: "r"(copy + 1) : "memory");
#pragma unroll
            for (int mb = 0; mb < 4; mb++)
#pragma unroll
                for (int nb = 0; nb < 4; nb++) {
                    int b0r = mb * 16 + g;
                    int u = 2 * tig;
                    float2 p0 = *(const float2*)&zc[nb * 512 + b0r * 8 + u];
                    float2 p1 = *(const float2*)&zc[nb * 512 + (b0r + 8) * 8 + u];
                    *(float2*)&zc[nb * 512 + b0r * 8 + u] =
                        make_float2(acc[mb][nb][0] + p0.x, acc[mb][nb][1] + p0.y);
                    *(float2*)&zc[nb * 512 + (b0r + 8) * 8 + u] =
                        make_float2(acc[mb][nb][2] + p1.x, acc[mb][nb][3] + p1.y);
                }
        }
        __syncthreads();   // all warps' polls passed + zs merged

        // ---- gates + state update (i, j, f, o; forget bias 1.0) ----
        float outv[2];
        bool fin[2];
#pragma unroll
        for (int s = 0; s < 2; s++) {
            int cell = tid + s * 256;
            int b = cell >> 3, u = cell & 7;
            int unit = j * 8 + u;
            float zi = zs[cell]        + zs[2048 + cell]
                     + zs[4096 + cell] + zs[6144 + cell] + xwv[s][0];
            float zj = zs[512 + cell]  + zs[2560 + cell]
                     + zs[4608 + cell] + zs[6656 + cell] + xwv[s][1];
            float zf = zs[1024 + cell] + zs[3072 + cell]
                     + zs[5120 + cell] + zs[7168 + cell] + xwv[s][2];
            float zo = zs[1536 + cell] + zs[3584 + cell]
                     + zs[5632 + cell] + zs[7680 + cell] + xwv[s][3];
            float nc = cst[s] * sigm(zf + 1.0f) + sigm(zi) * tanh_f(zj);
            float nh = tanh_f(nc) * sigm(zo);
            bool act = t < slr[s];
            if (act) { cst[s] = nc; hcur[s] = nh; }
            h_write[b * HH + unit] = __float2half(hcur[s]);
            fin[s] = (t == slr[s] - 1);      // final active step: h's defined value
            outv[s] = nh;
        }

        // ---- publish h availability (release), then off-path out stores ----
        __syncthreads();   // all threads' h_write stores happen-before release
        if (tid == 0)
            asm volatile("st.release.gpu.global.s32 [%0], %1;"
                         :: "l"(my_flag), "r"(t + 1) : "memory");
#pragma unroll
        for (int s = 0; s < 2; s++) {
            if (fin[s]) {
                int cell = tid + s * 256;
                out[(cell >> 3) * HH + j * 8 + (cell & 7)] = outv[s];
            }
        }
    }
}

// ---------------- launch ----------------
extern "C" void kernel_launch(void* const* d_in, const int* in_sizes, int n_in,
                              void* d_out, int out_size) {
    const float* x = (const float*)d_in[0];
    const int* seq_len = (const int*)d_in[1];
    const float* W = (const float*)d_in[2];
    const float* bias = (const float*)d_in[3];
    float* out = (float*)d_out;

    cudaFuncSetAttribute(lstm_persistent_kernel,
                         cudaFuncAttributeMaxDynamicSharedMemorySize, SM_TOT);
    cudaFuncSetAttribute(gemm_x_kernel,
                         cudaFuncAttributeMaxDynamicSharedMemorySize, 4 * GX_BUF);

    noop_kernel<<<1, 32>>>();   // keeps lstm at global launch #6 for ncu
    prep_kernel<<<8192, 256>>>(x, W, out);
    gemm_x_kernel<<<dim3(N4H / 128, MM / 128), 256, 4 * GX_BUF>>>(bias);
    lstm_persistent_kernel<<<GRID, 256, SM_TOT>>>(seq_len, out);
}